// round 2
// baseline (speedup 1.0000x reference)
#include <cuda_runtime.h>
#include <math.h>

// Shapes (fixed by the problem)
#define BB  2
#define NN  512
#define HID 128
#define DD  128   // Chebyshev orders (degree DD-1)

// Scratch (static device globals; no allocation)
__device__ float g_dmax;
__device__ float g_G[DD * HID];   // network(+Wo) evaluated at Chebyshev nodes
__device__ float g_C[DD * HID];   // Chebyshev coefficients of G

// ---------------------------------------------------------------------------
// Kernel 1: interval bound. Any pairwise distance <= 2*max||x|| (triangle ineq).
// ---------------------------------------------------------------------------
__global__ void dmax_kernel(const float* __restrict__ x) {
    __shared__ float red[256];
    float m = 0.0f;
    for (int t = threadIdx.x; t < BB * NN; t += 256) {
        float a = x[2 * t], b = x[2 * t + 1];
        m = fmaxf(m, fmaf(a, a, b * b));
    }
    red[threadIdx.x] = m;
    __syncthreads();
    for (int s = 128; s > 0; s >>= 1) {
        if (threadIdx.x < s) red[threadIdx.x] = fmaxf(red[threadIdx.x], red[threadIdx.x + s]);
        __syncthreads();
    }
    if (threadIdx.x == 0) g_dmax = 2.0f * sqrtf(red[0]) * 1.000001f + 1e-6f;
}

// ---------------------------------------------------------------------------
// Kernel 2: evaluate the exact fp32 network at DD Chebyshev nodes, fold Wo.
// 2 nodes per block (halves L2 weight traffic, 2-way ILP). 64 blocks x 128 thr.
// ---------------------------------------------------------------------------
__global__ void node_eval_kernel(
    const float* __restrict__ W10, const float* __restrict__ b10,
    const float* __restrict__ W20, const float* __restrict__ b20,
    const float* __restrict__ W11, const float* __restrict__ b11,
    const float* __restrict__ W21, const float* __restrict__ b21,
    const float* __restrict__ W12, const float* __restrict__ b12,
    const float* __restrict__ W22, const float* __restrict__ b22,
    const float* __restrict__ Wo)
{
    __shared__ float buf[2][2][HID];  // [pingpong][node][c]
    const int c  = threadIdx.x;
    const int m0 = 2 * blockIdx.x, m1 = m0 + 1;
    const float dmax = g_dmax;

    float d0 = 0.5f * (cospif((m0 + 0.5f) * (1.0f / DD)) + 1.0f) * dmax;
    float d1 = 0.5f * (cospif((m1 + 0.5f) * (1.0f / DD)) + 1.0f) * dmax;

    // layer 0 first half: a = silu(dist * W1_0 + b1_0)   (W1_0 is (1,HID))
    float a0 = fmaf(d0, W10[c], b10[c]);
    float a1 = fmaf(d1, W10[c], b10[c]);
    a0 = a0 / (1.0f + expf(-a0));
    a1 = a1 / (1.0f + expf(-a1));
    buf[0][0][c] = a0;
    buf[0][1][c] = a1;
    __syncthreads();

    const float* Ws[6] = {W20, W11, W21, W12, W22, Wo};
    const float* bs[6] = {b20, b11, b21, b12, b22, (const float*)0};
    int cur = 0;
    float h0 = 0.0f, h1 = 0.0f;
    #pragma unroll
    for (int l = 0; l < 6; l++) {
        float bbv = bs[l] ? bs[l][c] : 0.0f;
        h0 = bbv; h1 = bbv;
        const float* W = Ws[l];
        #pragma unroll 8
        for (int k = 0; k < HID; k++) {
            float w = W[k * HID + c];
            h0 = fmaf(buf[cur][0][k], w, h0);
            h1 = fmaf(buf[cur][1][k], w, h1);
        }
        if (l == 1 || l == 3) {   // silu after W1_1 and W1_2
            h0 = h0 / (1.0f + expf(-h0));
            h1 = h1 / (1.0f + expf(-h1));
        }
        __syncthreads();
        buf[cur ^ 1][0][c] = h0;
        buf[cur ^ 1][1][c] = h1;
        cur ^= 1;
        __syncthreads();
    }
    g_G[m0 * HID + c] = h0;
    g_G[m1 * HID + c] = h1;
}

// ---------------------------------------------------------------------------
// Kernel 3: DCT-II -> Chebyshev coefficients.
// Angle = pi * k(2m+1)/(2*DD) = pi * num/256, num integer (exact in fp32),
// reduced mod 512 (cospi period 2) -> cospif is fully accurate.
// ---------------------------------------------------------------------------
__global__ void dct_kernel() {
    const int k = blockIdx.x, c = threadIdx.x;
    float acc = 0.0f;
    #pragma unroll 8
    for (int m = 0; m < DD; m++) {
        int num = (k * (2 * m + 1)) & 511;
        float t = cospif((float)num * (1.0f / 256.0f));
        acc = fmaf(t, g_G[m * HID + c], acc);
    }
    float wgt = (k == 0) ? (1.0f / DD) : (2.0f / DD);
    g_C[k * HID + c] = acc * wgt;
}

// ---------------------------------------------------------------------------
// Kernel 4 (hot): per (b,i), accumulate s[k] = sum_j T_k(z_ij), then
// out = (1/N) * s @ C + bo.  1 warp per row; lanes split j 4-way for ILP so the
// latency-4 recurrence chain is issue-bound, not latency-bound.
// ---------------------------------------------------------------------------
__global__ __launch_bounds__(256, 1) void cheb_main_kernel(
    const float* __restrict__ x, const float* __restrict__ bo,
    float* __restrict__ out)
{
    __shared__ float sx[NN * 2];
    const int b = blockIdx.x >> 6;                    // 64 blocks per batch
    for (int t = threadIdx.x; t < NN * 2; t += 256) sx[t] = x[b * NN * 2 + t];
    __syncthreads();

    const int w    = threadIdx.x >> 5;
    const int lane = threadIdx.x & 31;
    const int i    = ((blockIdx.x & 63) << 3) + w;    // row within batch
    const float xi0 = sx[2 * i], xi1 = sx[2 * i + 1];
    const float inv_hd = 2.0f / g_dmax;

    float s[DD];
    #pragma unroll
    for (int k = 0; k < DD; k++) s[k] = 0.0f;

    #pragma unroll 1
    for (int j0 = 0; j0 < NN; j0 += 128) {
        const int ja = j0 + lane, jb = ja + 32, jc = ja + 64, jd = ja + 96;
        float dxa = xi0 - sx[2 * ja], dya = xi1 - sx[2 * ja + 1];
        float dxb = xi0 - sx[2 * jb], dyb = xi1 - sx[2 * jb + 1];
        float dxc = xi0 - sx[2 * jc], dyc = xi1 - sx[2 * jc + 1];
        float dxd = xi0 - sx[2 * jd], dyd = xi1 - sx[2 * jd + 1];
        float za = fmaf(sqrtf(fmaf(dxa, dxa, dya * dya)), inv_hd, -1.0f);
        float zb = fmaf(sqrtf(fmaf(dxb, dxb, dyb * dyb)), inv_hd, -1.0f);
        float zc = fmaf(sqrtf(fmaf(dxc, dxc, dyc * dyc)), inv_hd, -1.0f);
        float zd = fmaf(sqrtf(fmaf(dxd, dxd, dyd * dyd)), inv_hd, -1.0f);
        za = fminf(fmaxf(za, -1.0f), 1.0f);
        zb = fminf(fmaxf(zb, -1.0f), 1.0f);
        zc = fminf(fmaxf(zc, -1.0f), 1.0f);
        zd = fminf(fmaxf(zd, -1.0f), 1.0f);

        s[1] += (za + zb) + (zc + zd);
        float t0a = 1.0f, t1a = za, z2a = za + za;
        float t0b = 1.0f, t1b = zb, z2b = zb + zb;
        float t0c = 1.0f, t1c = zc, z2c = zc + zc;
        float t0d = 1.0f, t1d = zd, z2d = zd + zd;
        #pragma unroll
        for (int k = 2; k < DD; k++) {
            float ta = fmaf(z2a, t1a, -t0a); t0a = t1a; t1a = ta;
            float tb = fmaf(z2b, t1b, -t0b); t0b = t1b; t1b = tb;
            float tc = fmaf(z2c, t1c, -t0c); t0c = t1c; t1c = tc;
            float td = fmaf(z2d, t1d, -t0d); t0d = t1d; t1d = td;
            s[k] += (ta + tb) + (tc + td);
        }
    }

    // warp butterfly reduce (s[0] is exactly NN: T_0 == 1)
    #pragma unroll
    for (int off = 16; off > 0; off >>= 1) {
        #pragma unroll
        for (int k = 1; k < DD; k++) s[k] += __shfl_xor_sync(0xffffffffu, s[k], off);
    }
    s[0] = (float)NN;

    // out_c = (1/N) * sum_k s[k]*C[k][c] + bo[c]; each lane owns 4 columns
    const float sc = 1.0f / (float)NN;
    const int c0 = lane * 4;
    float4 acc = make_float4(bo[c0], bo[c0 + 1], bo[c0 + 2], bo[c0 + 3]);
    #pragma unroll 8
    for (int k = 0; k < DD; k++) {
        float4 wv = *reinterpret_cast<const float4*>(&g_C[k * HID + c0]);
        float sk = s[k] * sc;
        acc.x = fmaf(sk, wv.x, acc.x);
        acc.y = fmaf(sk, wv.y, acc.y);
        acc.z = fmaf(sk, wv.z, acc.z);
        acc.w = fmaf(sk, wv.w, acc.w);
    }
    const int gi = b * NN + i;
    reinterpret_cast<float4*>(out)[gi * (HID / 4) + lane] = acc;
}

// ---------------------------------------------------------------------------
// Launch: 4 graph-capturable kernels, stream-ordered dependencies.
// Input order: x, W1_0,b1_0,W2_0,b2_0, W1_1,b1_1,W2_1,b2_1, W1_2,b1_2,W2_2,b2_2, Wo,bo
// ---------------------------------------------------------------------------
extern "C" void kernel_launch(void* const* d_in, const int* in_sizes, int n_in,
                              void* d_out, int out_size)
{
    const float* x   = (const float*)d_in[0];
    const float* W10 = (const float*)d_in[1];
    const float* b10 = (const float*)d_in[2];
    const float* W20 = (const float*)d_in[3];
    const float* b20 = (const float*)d_in[4];
    const float* W11 = (const float*)d_in[5];
    const float* b11 = (const float*)d_in[6];
    const float* W21 = (const float*)d_in[7];
    const float* b21 = (const float*)d_in[8];
    const float* W12 = (const float*)d_in[9];
    const float* b12 = (const float*)d_in[10];
    const float* W22 = (const float*)d_in[11];
    const float* b22 = (const float*)d_in[12];
    const float* Wo  = (const float*)d_in[13];
    const float* bo  = (const float*)d_in[14];
    float* out = (float*)d_out;

    dmax_kernel<<<1, 256>>>(x);
    node_eval_kernel<<<DD / 2, HID>>>(W10, b10, W20, b20, W11, b11,
                                      W21, b21, W12, b12, W22, b22, Wo);
    dct_kernel<<<DD, HID>>>();
    cheb_main_kernel<<<(BB * NN) / 8, 256>>>(x, bo, out);
}

// round 3
// speedup vs baseline: 1.4649x; 1.4649x over previous
#include <cuda_runtime.h>
#include <math.h>

// Shapes (fixed by the problem)
#define BB  2
#define NN  512
#define HID 128
#define DD  64    // Chebyshev orders (degree DD-1); pole analysis gives rho~2 -> 2^-64 truncation

// Scratch (static device globals; no allocation)
__device__ float g_G[DD * HID];   // network(+Wo) evaluated at Chebyshev nodes
__device__ float g_C[DD * HID];   // Chebyshev coefficients of G

// ---------------------------------------------------------------------------
// Deterministic per-block dmax (identical result in every 128-thread block):
// any pairwise distance <= 2*max||x|| by triangle inequality.
// ---------------------------------------------------------------------------
__device__ __forceinline__ float block_dmax(const float* __restrict__ x, float* red) {
    float m = 0.0f;
    for (int t = threadIdx.x; t < BB * NN; t += 128) {
        float a = x[2 * t], b = x[2 * t + 1];
        m = fmaxf(m, fmaf(a, a, b * b));
    }
    red[threadIdx.x] = m;
    __syncthreads();
    #pragma unroll
    for (int s = 64; s > 0; s >>= 1) {
        if (threadIdx.x < s) red[threadIdx.x] = fmaxf(red[threadIdx.x], red[threadIdx.x + s]);
        __syncthreads();
    }
    float r = 2.0f * sqrtf(red[0]) * 1.000001f + 1e-6f;
    __syncthreads();
    return r;
}

// ---------------------------------------------------------------------------
// Kernel 1: evaluate the exact fp32 network at DD Chebyshev nodes, fold Wo.
// 2 nodes per block. DD/2 = 32 blocks x 128 threads. Computes dmax inline.
// ---------------------------------------------------------------------------
__global__ __launch_bounds__(HID) void node_eval_kernel(
    const float* __restrict__ x,
    const float* __restrict__ W10, const float* __restrict__ b10,
    const float* __restrict__ W20, const float* __restrict__ b20,
    const float* __restrict__ W11, const float* __restrict__ b11,
    const float* __restrict__ W21, const float* __restrict__ b21,
    const float* __restrict__ W12, const float* __restrict__ b12,
    const float* __restrict__ W22, const float* __restrict__ b22,
    const float* __restrict__ Wo)
{
    __shared__ float red[128];
    __shared__ float buf[2][2][HID];  // [pingpong][node][c]
    const float dmax = block_dmax(x, red);

    const int c  = threadIdx.x;
    const int m0 = 2 * blockIdx.x, m1 = m0 + 1;

    float d0 = 0.5f * (cospif((m0 + 0.5f) * (1.0f / DD)) + 1.0f) * dmax;
    float d1 = 0.5f * (cospif((m1 + 0.5f) * (1.0f / DD)) + 1.0f) * dmax;

    // layer 0 first half: a = silu(dist * W1_0 + b1_0)   (W1_0 is (1,HID))
    float a0 = fmaf(d0, W10[c], b10[c]);
    float a1 = fmaf(d1, W10[c], b10[c]);
    a0 = a0 / (1.0f + expf(-a0));
    a1 = a1 / (1.0f + expf(-a1));
    buf[0][0][c] = a0;
    buf[0][1][c] = a1;
    __syncthreads();

    const float* Ws[6] = {W20, W11, W21, W12, W22, Wo};
    const float* bs[6] = {b20, b11, b21, b12, b22, (const float*)0};
    int cur = 0;
    float h0 = 0.0f, h1 = 0.0f;
    #pragma unroll
    for (int l = 0; l < 6; l++) {
        float bbv = bs[l] ? bs[l][c] : 0.0f;
        h0 = bbv; h1 = bbv;
        const float* W = Ws[l];
        #pragma unroll 8
        for (int k = 0; k < HID; k++) {
            float w = W[k * HID + c];
            h0 = fmaf(buf[cur][0][k], w, h0);
            h1 = fmaf(buf[cur][1][k], w, h1);
        }
        if (l == 1 || l == 3) {   // silu after W1_1 and W1_2
            h0 = h0 / (1.0f + expf(-h0));
            h1 = h1 / (1.0f + expf(-h1));
        }
        __syncthreads();
        buf[cur ^ 1][0][c] = h0;
        buf[cur ^ 1][1][c] = h1;
        cur ^= 1;
        __syncthreads();
    }
    g_G[m0 * HID + c] = h0;
    g_G[m1 * HID + c] = h1;
}

// ---------------------------------------------------------------------------
// Kernel 2: DCT-II -> Chebyshev coefficients.
// Angle = pi * k(2m+1)/(2*DD) = pi*num/128, num integer exact in fp32,
// reduced mod 256 (cospi period 2) -> cospif is bit-accurate.
// ---------------------------------------------------------------------------
__global__ __launch_bounds__(HID) void dct_kernel() {
    const int k = blockIdx.x, c = threadIdx.x;
    float acc = 0.0f;
    #pragma unroll 8
    for (int m = 0; m < DD; m++) {
        int num = (k * (2 * m + 1)) & 255;
        float t = cospif((float)num * (1.0f / 128.0f));
        acc = fmaf(t, g_G[m * HID + c], acc);
    }
    float wgt = (k == 0) ? (1.0f / DD) : (2.0f / DD);
    g_C[k * HID + c] = acc * wgt;
}

// ---------------------------------------------------------------------------
// Kernel 3 (hot): per (b,i), s[k] = sum_j T_k(z_ij); out = (1/N) s@C + bo.
// 1 warp per row, 4 rows (128 thr) per block, 256 blocks.
// 4 independent recurrence chains per lane hide FMA lat-4.
// Cross-lane reduction = reduce-scatter butterfly (62 shfl instead of ~635):
// each stage exchanges+folds half the register array; after 5 stages lane L
// holds fully-reduced coefficients k = 2L and 2L+1.
// ---------------------------------------------------------------------------
__global__ __launch_bounds__(128, 4) void cheb_main_kernel(
    const float* __restrict__ x, const float* __restrict__ bo,
    float* __restrict__ out)
{
    __shared__ float red[128];
    __shared__ float sx[NN * 2];
    __shared__ float sred[4][DD];          // reduced s per warp

    const float inv_hd = 2.0f / block_dmax(x, red);

    const int b = blockIdx.x >> 7;         // 128 blocks per batch
    for (int t = threadIdx.x; t < NN * 2; t += 128) sx[t] = x[b * NN * 2 + t];
    __syncthreads();

    const int w    = threadIdx.x >> 5;
    const int lane = threadIdx.x & 31;
    const int i    = ((blockIdx.x & 127) << 2) + w;   // row within batch
    const float xi0 = sx[2 * i], xi1 = sx[2 * i + 1];

    float s[DD];
    #pragma unroll
    for (int k = 0; k < DD; k++) s[k] = 0.0f;

    #pragma unroll 1
    for (int j0 = 0; j0 < NN; j0 += 128) {
        const int ja = j0 + lane, jb = ja + 32, jc = ja + 64, jd = ja + 96;
        float dxa = xi0 - sx[2 * ja], dya = xi1 - sx[2 * ja + 1];
        float dxb = xi0 - sx[2 * jb], dyb = xi1 - sx[2 * jb + 1];
        float dxc = xi0 - sx[2 * jc], dyc = xi1 - sx[2 * jc + 1];
        float dxd = xi0 - sx[2 * jd], dyd = xi1 - sx[2 * jd + 1];
        float za = fmaf(sqrtf(fmaf(dxa, dxa, dya * dya)), inv_hd, -1.0f);
        float zb = fmaf(sqrtf(fmaf(dxb, dxb, dyb * dyb)), inv_hd, -1.0f);
        float zc = fmaf(sqrtf(fmaf(dxc, dxc, dyc * dyc)), inv_hd, -1.0f);
        float zd = fmaf(sqrtf(fmaf(dxd, dxd, dyd * dyd)), inv_hd, -1.0f);
        za = fminf(fmaxf(za, -1.0f), 1.0f);
        zb = fminf(fmaxf(zb, -1.0f), 1.0f);
        zc = fminf(fmaxf(zc, -1.0f), 1.0f);
        zd = fminf(fmaxf(zd, -1.0f), 1.0f);

        s[1] += (za + zb) + (zc + zd);
        float t0a = 1.0f, t1a = za, z2a = za + za;
        float t0b = 1.0f, t1b = zb, z2b = zb + zb;
        float t0c = 1.0f, t1c = zc, z2c = zc + zc;
        float t0d = 1.0f, t1d = zd, z2d = zd + zd;
        #pragma unroll
        for (int k = 2; k < DD; k++) {
            float ta = fmaf(z2a, t1a, -t0a); t0a = t1a; t1a = ta;
            float tb = fmaf(z2b, t1b, -t0b); t0b = t1b; t1b = tb;
            float tc = fmaf(z2c, t1c, -t0c); t0c = t1c; t1c = tc;
            float td = fmaf(z2d, t1d, -t0d); t0d = t1d; t1d = td;
            s[k] += (ta + tb) + (tc + td);
        }
    }
    // T_0 == 1: each lane processed NN/32 = 16 source nodes
    s[0] = (float)(NN / 32);

    // reduce-scatter butterfly: after 5 stages lane holds k = 2*lane + {0,1}
    int len = DD / 2;
    #pragma unroll
    for (int off = 16; off > 0; off >>= 1) {
        const bool hi = (lane & off) != 0;
        #pragma unroll
        for (int k = 0; k < 32; k++) {     // bounded by first-stage len
            if (k >= len) break;
            float send = hi ? s[k] : s[k + len];
            float recv = __shfl_xor_sync(0xffffffffu, send, off);
            s[k] = (hi ? s[k + len] : s[k]) + recv;
        }
        len >>= 1;
    }
    sred[w][2 * lane]     = s[0];
    sred[w][2 * lane + 1] = s[1];
    __syncwarp();

    // out_c = (1/N) * sum_k s[k]*C[k][c] + bo[c]; each lane owns 4 columns
    const float sc = 1.0f / (float)NN;
    const int c0 = lane * 4;
    float4 acc = make_float4(bo[c0], bo[c0 + 1], bo[c0 + 2], bo[c0 + 3]);
    #pragma unroll 8
    for (int k = 0; k < DD; k++) {
        float4 wv = *reinterpret_cast<const float4*>(&g_C[k * HID + c0]);
        float sk = sred[w][k] * sc;
        acc.x = fmaf(sk, wv.x, acc.x);
        acc.y = fmaf(sk, wv.y, acc.y);
        acc.z = fmaf(sk, wv.z, acc.z);
        acc.w = fmaf(sk, wv.w, acc.w);
    }
    const int gi = b * NN + i;
    reinterpret_cast<float4*>(out)[gi * (HID / 4) + lane] = acc;
}

// ---------------------------------------------------------------------------
// Launch: 3 graph-capturable kernels, stream-ordered dependencies.
// Input order: x, W1_0,b1_0,W2_0,b2_0, W1_1,b1_1,W2_1,b2_1, W1_2,b1_2,W2_2,b2_2, Wo,bo
// ---------------------------------------------------------------------------
extern "C" void kernel_launch(void* const* d_in, const int* in_sizes, int n_in,
                              void* d_out, int out_size)
{
    const float* x   = (const float*)d_in[0];
    const float* W10 = (const float*)d_in[1];
    const float* b10 = (const float*)d_in[2];
    const float* W20 = (const float*)d_in[3];
    const float* b20 = (const float*)d_in[4];
    const float* W11 = (const float*)d_in[5];
    const float* b11 = (const float*)d_in[6];
    const float* W21 = (const float*)d_in[7];
    const float* b21 = (const float*)d_in[8];
    const float* W12 = (const float*)d_in[9];
    const float* b12 = (const float*)d_in[10];
    const float* W22 = (const float*)d_in[11];
    const float* b22 = (const float*)d_in[12];
    const float* Wo  = (const float*)d_in[13];
    const float* bo  = (const float*)d_in[14];
    float* out = (float*)d_out;

    node_eval_kernel<<<DD / 2, HID>>>(x, W10, b10, W20, b20, W11, b11,
                                      W21, b21, W12, b12, W22, b22, Wo);
    dct_kernel<<<DD, HID>>>();
    cheb_main_kernel<<<(BB * NN) / 4, 128>>>(x, bo, out);
}